// round 17
// baseline (speedup 1.0000x reference)
#include <cuda_runtime.h>
#include <cuda_bf16.h>
#include <cstdint>

#define BATCH 8
#define TLEN 256
#define DIM 256
#define NSTEP 12
#define NNEG 100
#define MROWS 2048
#define NCOLS 3072
#define NPART (NSTEP * MROWS)

__device__ float g_C[MROWS * NCOLS];                 // raw GEMM output (f32)
__device__ uint32_t g_tn8[MROWS * 64];               // normalized targets, s8x4
__device__ float g_part[NPART];                      // per-sample loss partials
__device__ uint32_t g_Abf[MROWS * DIM / 2];          // ctx in bf16x2, k-major
__device__ uint32_t g_Bbf[NCOLS * DIM / 2];          // W   in bf16x2, k-major
__device__ int g_tick;                               // ticket for fused reduce

// ---------------------------------------------------------------------------
// warp reductions (butterfly shfl — f32 redux does NOT exist on sm_103a)
// ---------------------------------------------------------------------------
__device__ __forceinline__ float wsum(float v) {
#pragma unroll
    for (int o = 16; o; o >>= 1) v += __shfl_xor_sync(0xffffffffu, v, o);
    return v;
}
__device__ __forceinline__ float wmax(float v) {
#pragma unroll
    for (int o = 16; o; o >>= 1) v = fmaxf(v, __shfl_xor_sync(0xffffffffu, v, o));
    return v;
}

// ---------------------------------------------------------------------------
// Threefry-2x32 (exact JAX rotation/key schedule)
// ---------------------------------------------------------------------------
__device__ __forceinline__ void tf2x32(uint32_t k0, uint32_t k1,
                                       uint32_t x0, uint32_t x1,
                                       uint32_t &o0, uint32_t &o1) {
    uint32_t ks2 = k0 ^ k1 ^ 0x1BD11BDAu;
    x0 += k0; x1 += k1;
#define TFR(r) { x0 += x1; x1 = __funnelshift_l(x1, x1, (r)); x1 ^= x0; }
    TFR(13) TFR(15) TFR(26) TFR(6)   x0 += k1;  x1 += ks2 + 1u;
    TFR(17) TFR(29) TFR(16) TFR(24)  x0 += ks2; x1 += k0 + 2u;
    TFR(13) TFR(15) TFR(26) TFR(6)   x0 += k0;  x1 += k1 + 3u;
    TFR(17) TFR(29) TFR(16) TFR(24)  x0 += k1;  x1 += ks2 + 4u;
    TFR(13) TFR(15) TFR(26) TFR(6)   x0 += ks2; x1 += k0 + 5u;
#undef TFR
    o0 = x0; o1 = x1;
}

__device__ __forceinline__ uint32_t tf_bits32(uint32_t k0, uint32_t k1, uint32_t i) {
    uint32_t a, b;
    tf2x32(k0, k1, 0u, i, a, b);
    return a ^ b;
}

// ---------------------------------------------------------------------------
// bf16x2 / int8 helpers
// ---------------------------------------------------------------------------
__device__ __forceinline__ uint32_t f2_to_bf2(float lo, float hi) {
    __nv_bfloat162 p = __floats2bfloat162_rn(lo, hi);   // .x = lo (low half)
    return *reinterpret_cast<uint32_t*>(&p);
}
// pack 4 floats (already scaled to [-127,127]) as s8x4
__device__ __forceinline__ uint32_t pack_s8x4(float a, float b, float c, float d) {
    int ia = __float2int_rn(a), ib = __float2int_rn(b);
    int ic = __float2int_rn(c), id = __float2int_rn(d);
    return (uint32_t)(ia & 0xff) | ((uint32_t)(ib & 0xff) << 8) |
           ((uint32_t)(ic & 0xff) << 16) | ((uint32_t)(id & 0xff) << 24);
}

// ---------------------------------------------------------------------------
// async copy / ldmatrix / mma primitives
// ---------------------------------------------------------------------------
__device__ __forceinline__ void cpa16(uint32_t dst, const void* src) {
    asm volatile("cp.async.cg.shared.global [%0], [%1], 16;"
                 :: "r"(dst), "l"(src));
}
__device__ __forceinline__ void ldsm4(uint32_t &r0, uint32_t &r1,
                                      uint32_t &r2, uint32_t &r3, uint32_t a) {
    asm volatile("ldmatrix.sync.aligned.m8n8.x4.shared.b16 {%0,%1,%2,%3}, [%4];"
                 : "=r"(r0), "=r"(r1), "=r"(r2), "=r"(r3) : "r"(a));
}
__device__ __forceinline__ void mma_bf16(float* d, const uint32_t* a,
                                         uint32_t b0, uint32_t b1) {
    asm("mma.sync.aligned.m16n8k16.row.col.f32.bf16.bf16.f32 "
        "{%0,%1,%2,%3}, {%4,%5,%6,%7}, {%8,%9}, {%0,%1,%2,%3};"
        : "+f"(d[0]), "+f"(d[1]), "+f"(d[2]), "+f"(d[3])
        : "r"(a[0]), "r"(a[1]), "r"(a[2]), "r"(a[3]), "r"(b0), "r"(b1));
}

// ---------------------------------------------------------------------------
// Kernel 1 (fused prep): blockIdx branches over three independent jobs:
//   [0,256)        normalize target rows -> s8 (uniform scale 127)
//   [256,1280)     ctx  fp32 -> bf16x2
//   [1280,2816)    W    fp32 -> bf16x2
// ---------------------------------------------------------------------------
__global__ __launch_bounds__(256) void k_prep(const float* __restrict__ tgt,
                                              const float* __restrict__ ctx,
                                              const float* __restrict__ W) {
    int blk = blockIdx.x;
    int tid = threadIdx.x;
    if (blk < 256) {
        int gw = blk * 8 + (tid >> 5);            // target row 0..2047
        int lane = tid & 31;
        const float4* r = reinterpret_cast<const float4*>(tgt + (size_t)gw * DIM);
        float4 a = r[lane * 2];
        float4 b = r[lane * 2 + 1];
        float ss = a.x*a.x + a.y*a.y + a.z*a.z + a.w*a.w
                 + b.x*b.x + b.y*b.y + b.z*b.z + b.w*b.w;
        ss = wsum(ss);
        float q = 127.0f / fmaxf(sqrtf(ss), 1e-12f);
        uint2 u;
        u.x = pack_s8x4(a.x * q, a.y * q, a.z * q, a.w * q);
        u.y = pack_s8x4(b.x * q, b.y * q, b.z * q, b.w * q);
        reinterpret_cast<uint2*>(g_tn8 + (size_t)gw * 64)[lane] = u;
    } else if (blk < 1280) {
        int i = (blk - 256) * 256 + tid;          // ctx pair index
        float2 v = reinterpret_cast<const float2*>(ctx)[i];
        g_Abf[i] = f2_to_bf2(v.x, v.y);
    } else {
        int i = (blk - 1280) * 256 + tid;         // W pair index
        float2 v = reinterpret_cast<const float2*>(W)[i];
        g_Bbf[i] = f2_to_bf2(v.x, v.y);
    }
}

// ---------------------------------------------------------------------------
// Kernel 2: C[2048,3072] = A[2048,256] * B[3072,256]^T via smem-tiled HMMA.
//   Block tile 128x128, 8 warps (warp = 32x64), K chunks of 32, double-
//   buffered cp.async.cg, fragments via ldmatrix.x4. Smem rows padded to
//   80B -> LDSM 8-row address sets hit 8 distinct 16B slots (conflict-free).
// ---------------------------------------------------------------------------
#define KCHUNKS 8
#define ROWB 80                      // padded row stride in bytes (32 bf16 + pad)
#define TILEB (128 * ROWB)           // 10240 B per tile buffer

__global__ __launch_bounds__(256) void k_mma() {
    __shared__ uint8_t sA[2][TILEB];
    __shared__ uint8_t sB[2][TILEB];

    int tid = threadIdx.x;
    int lane = tid & 31, w = tid >> 5;
    int bm = blockIdx.y * 128;       // M block
    int bn = blockIdx.x * 128;       // N block
    int wmo = (w & 3) * 32;          // warp m-offset in tile
    int wno = (w >> 2) * 64;         // warp n-offset in tile

    uint32_t sAu = (uint32_t)__cvta_generic_to_shared(&sA[0][0]);
    uint32_t sBu = (uint32_t)__cvta_generic_to_shared(&sB[0][0]);

    // copy indexing: 2 rows per thread per tile (128 rows x 4 segs of 16B)
    int crow = tid >> 2, cseg = tid & 3;
    const uint32_t* gA = g_Abf + (size_t)(bm + crow) * 128 + cseg * 4;
    const uint32_t* gB = g_Bbf + (size_t)(bn + crow) * 128 + cseg * 4;
    uint32_t dA = sAu + crow * ROWB + cseg * 16;
    uint32_t dB = sBu + crow * ROWB + cseg * 16;

#define COPY_CHUNK(c, buf)                                                    \
    {                                                                         \
        cpa16(dA + (buf) * TILEB, gA + (c) * 16);                             \
        cpa16(dA + (buf) * TILEB + 64 * ROWB, gA + 64 * 128 + (c) * 16);      \
        cpa16(dB + (buf) * TILEB, gB + (c) * 16);                            \
        cpa16(dB + (buf) * TILEB + 64 * ROWB, gB + 64 * 128 + (c) * 16);      \
        asm volatile("cp.async.commit_group;");                               \
    }

    float acc[2][8][4];
#pragma unroll
    for (int i = 0; i < 2; i++)
#pragma unroll
        for (int j = 0; j < 8; j++)
#pragma unroll
            for (int k = 0; k < 4; k++) acc[i][j][k] = 0.0f;

    int gh = (lane >> 3) & 1;        // ldmatrix address group: row half
    int kh = lane >> 4;              // ldmatrix address group: k half
    int lr = lane & 7;               // row within 8
    int qr = lane >> 2, kc = lane & 3;

    COPY_CHUNK(0, 0)

    for (int c = 0; c < KCHUNKS; c++) {
        int buf = c & 1;
        if (c < KCHUNKS - 1) COPY_CHUNK(c + 1, buf ^ 1)
        if (c < KCHUNKS - 1) asm volatile("cp.async.wait_group 1;");
        else                 asm volatile("cp.async.wait_group 0;");
        __syncthreads();

        uint32_t aBase = sAu + buf * TILEB;
        uint32_t bBase = sBu + buf * TILEB;
#pragma unroll
        for (int c16 = 0; c16 < 2; c16++) {
            uint32_t kbyte = c16 * 32 + kh * 16;
            uint32_t a[2][4];
#pragma unroll
            for (int mf = 0; mf < 2; mf++) {
                uint32_t addr = aBase + (wmo + mf * 16 + gh * 8 + lr) * ROWB + kbyte;
                ldsm4(a[mf][0], a[mf][1], a[mf][2], a[mf][3], addr);
            }
#pragma unroll
            for (int nfp = 0; nfp < 4; nfp++) {
                uint32_t b0, b1, b2, b3;
                uint32_t addr = bBase + (wno + nfp * 16 + gh * 8 + lr) * ROWB + kbyte;
                ldsm4(b0, b1, b2, b3, addr);
                mma_bf16(acc[0][nfp * 2],     a[0], b0, b2);
                mma_bf16(acc[0][nfp * 2 + 1], a[0], b1, b3);
                mma_bf16(acc[1][nfp * 2],     a[1], b0, b2);
                mma_bf16(acc[1][nfp * 2 + 1], a[1], b1, b3);
            }
        }
        __syncthreads();
    }
#undef COPY_CHUNK

    // Epilogue: D row r: c0,c1 at (qr, 2kc); c2,c3 at row +8. float2 stores.
#pragma unroll
    for (int mf = 0; mf < 2; mf++) {
#pragma unroll
        for (int nf = 0; nf < 8; nf++) {
            float* d = acc[mf][nf];
            int r = bm + wmo + mf * 16 + qr;
            int cc = bn + wno + nf * 8 + kc * 2;
            *reinterpret_cast<float2*>(g_C + (size_t)r * NCOLS + cc) =
                make_float2(d[0], d[1]);
            *reinterpret_cast<float2*>(g_C + (size_t)(r + 8) * NCOLS + cc) =
                make_float2(d[2], d[3]);
        }
    }
}

// ---------------------------------------------------------------------------
// Kernel 3: per-(step,b,t) InfoNCE partial loss with fused query prep AND
//   fused final reduction (last-block ticket). Prologue: block reads its f32
//   query row, adds bias, block-reduces the norm, quantizes to s8 in smem
//   (2 barriers). Mainloop: warp-per-item s8 gather, 2 DP4A/lane, exact
//   int32 partials, LDS.128 reduce, fully unrolled. Epilogue: ticket; the
//   last block sums g_part (fixed order -> deterministic) into out[0].
// ---------------------------------------------------------------------------
__global__ __launch_bounds__(256) void k_loss(const float* __restrict__ bias,
                                              float* __restrict__ out) {
    int s = blockIdx.y + 1;           // step 1..12
    int T2 = TLEN - s;
    int bt = blockIdx.x;              // 0..2047
    int b = bt >> 8, t = bt & 255;
    int tid = threadIdx.x;
    __shared__ __align__(16) int sp[101 * 36];  // per-lane int partials
    __shared__ float logits[101];
    __shared__ int sidx[104];         // row * 32 (uint2 units); 101..103 = pad
    __shared__ uint32_t cst[3];       // k0, k1, mult
    __shared__ float snorm[8];        // 8 warp sq-sums
    __shared__ __align__(8) int8_t sq8[256];    // quantized query row
    __shared__ int sdone;
    int lane = tid & 31, w = tid >> 5;
    bool valid = (t < T2);            // block-uniform

    if (valid) {
        uint32_t span = (uint32_t)(BATCH * T2);

        // --- phase 0: query element + warp sq-sums + PRNG constants
        float qv = g_C[(size_t)bt * NCOLS + (size_t)(s - 1) * DIM + tid]
                 + bias[(size_t)(s - 1) * DIM + tid];
        float ssq = wsum(qv * qv);
        if (lane == 0) snorm[w] = ssq;
        if (tid == 0) {
            uint32_t k0, k1;
            tf2x32(0u, 1234u, 0u, (uint32_t)s, k0, k1);  // fold_in(key(1234), s)
            uint32_t m16 = 65536u % span;
            cst[0] = k0; cst[1] = k1; cst[2] = (m16 * m16) % span;
        }
        __syncthreads();

        // --- phase 1: negative indices (threads 0..103) + everyone
        //     finalizes the norm redundantly and quantizes its own byte
        if (tid < 104) {
            int row = 0;              // pad rows -> row 0 (discarded)
            if (tid == 0) {
                row = b * TLEN + t + s;   // positive
            } else if (tid < 101) {
                uint32_t k0 = cst[0], k1 = cst[1], mult = cst[2];
                uint32_t n = span * NNEG;
                uint32_t i = (uint32_t)((b * T2 + t) * NNEG + (tid - 1));
                uint32_t hi = tf_bits32(k0, k1, i);
                uint32_t lo = tf_bits32(k0, k1, n + i);
                uint32_t off = ((hi % span) * mult + (lo % span)) % span;
                uint32_t b2 = off / (uint32_t)T2;
                uint32_t t2 = off - b2 * (uint32_t)T2;
                row = (int)(b2 * TLEN + (uint32_t)s + t2);
            }
            sidx[tid] = row * 32;
        }
        {
            float tot = ((snorm[0] + snorm[1]) + (snorm[2] + snorm[3]))
                      + ((snorm[4] + snorm[5]) + (snorm[6] + snorm[7]));
            float qsc = 127.0f / fmaxf(sqrtf(tot), 1e-12f);
            sq8[tid] = (int8_t)__float2int_rn(qv * qsc);
        }
        __syncthreads();

        // --- phase 2: gather + dot mainloop
        uint2 q = reinterpret_cast<const uint2*>(sq8)[lane];
        const uint2* tn2 = reinterpret_cast<const uint2*>(g_tn8);
#pragma unroll
        for (int it = 0; it < 13; it++) {
            int g = it * 8 + w;       // item id 0..103; uniform across warp
            uint2 v = __ldg(tn2 + sidx[g] + lane);
            int d = __dp4a((int)v.x, (int)q.x, __dp4a((int)v.y, (int)q.y, 0));
            if (g < 101) sp[g * 36 + lane] = d;   // warp-uniform predicate
        }
        __syncthreads();

        // --- phase 3: reduce 32 int partials per item with LDS.128
        if (tid < 101) {
            const int4* r4 = reinterpret_cast<const int4*>(sp + tid * 36);
            int4 a0 = r4[0], a1 = r4[1], a2 = r4[2], a3 = r4[3];
            int4 a4 = r4[4], a5 = r4[5], a6 = r4[6], a7 = r4[7];
            int s0 = (a0.x + a0.y) + (a0.z + a0.w);
            int s1 = (a1.x + a1.y) + (a1.z + a1.w);
            int s2 = (a2.x + a2.y) + (a2.z + a2.w);
            int s3 = (a3.x + a3.y) + (a3.z + a3.w);
            int s4 = (a4.x + a4.y) + (a4.z + a4.w);
            int s5 = (a5.x + a5.y) + (a5.z + a5.w);
            int s6 = (a6.x + a6.y) + (a6.z + a6.w);
            int s7 = (a7.x + a7.y) + (a7.z + a7.w);
            int tot = (((s0 + s1) + (s2 + s3)) + ((s4 + s5) + (s6 + s7)));
            logits[tid] = (float)tot * (10.0f / 16129.0f);   // /TEMP / 127^2
        }
        __syncthreads();

        // --- phase 4: log-softmax + partial write
        if (w == 0) {
            float mx = -1e30f;
            for (int i = lane; i < 101; i += 32) mx = fmaxf(mx, logits[i]);
            mx = wmax(mx);
            float sum = 0.0f;
            for (int i = lane; i < 101; i += 32) sum += __expf(logits[i] - mx);
            sum = wsum(sum);
            if (lane == 0) {
                float lse = mx + __logf(sum);
                g_part[(size_t)(s - 1) * MROWS + bt] =
                    (lse - logits[0]) / (float)(NSTEP * BATCH * T2);
            }
        }
    }

    // --- epilogue: ticket; last block performs the deterministic reduction
    if (tid == 0) {
        if (!valid) g_part[(size_t)(s - 1) * MROWS + bt] = 0.0f;
        __threadfence();
        int old = atomicAdd(&g_tick, 1);
        sdone = (old == NPART - 1);
    }
    __syncthreads();
    if (sdone) {
        __threadfence();
        __shared__ float sm[256];
        const float4* p4 = reinterpret_cast<const float4*>(g_part);
        float acc = 0.0f;
        for (int i = tid; i < NPART / 4; i += 256) {
            float4 v = p4[i];
            acc += (v.x + v.y) + (v.z + v.w);
        }
        sm[tid] = acc;
        __syncthreads();
        for (int o = 128; o; o >>= 1) {
            if (tid < o) sm[tid] += sm[tid + o];
            __syncthreads();
        }
        if (tid == 0) {
            out[0] = sm[0];
            g_tick = 0;               // reset for next graph replay
        }
    }
}

// ---------------------------------------------------------------------------
extern "C" void kernel_launch(void* const* d_in, const int* in_sizes, int n_in,
                              void* d_out, int out_size) {
    const float* ctx  = (const float*)d_in[0];
    const float* tgt  = (const float*)d_in[1];
    const float* W    = (const float*)d_in[2];
    const float* bias = (const float*)d_in[3];
    float* out = (float*)d_out;

    k_prep<<<2816, 256>>>(tgt, ctx, W);
    k_mma<<<dim3(NCOLS / 128, MROWS / 128), 256>>>();
    k_loss<<<dim3(MROWS, NSTEP), 256>>>(bias, out);
}